// round 6
// baseline (speedup 1.0000x reference)
#include <cuda_runtime.h>
#include <cstdint>

#define GRID_G   180
#define NV       (GRID_G * GRID_G)            // 32400
#define CELLS    (179 * 179)                  // 32041
#define NF_BASE  (2 * CELLS)                  // 64082 faces
#define B0       (3 * CELLS)                  // 96123
#define NUM_NEW  (B0 + 358)                   // 96481
#define DIM      256
#define BATCH    4
#define ROWS_OUT (NV + NUM_NEW)               // 128881
#define NFACES4  (4 * NF_BASE)                // 256328
#define NEDGE    (12 * NF_BASE)               // 768984

#define OUT_FEAT_ELEMS   ((size_t)BATCH * ROWS_OUT * DIM)      // 131,974,144
#define OUT_NF_ELEMS     ((size_t)BATCH * NFACES4 * 3)         // 3,075,936

#define PER_B_OUT4   (ROWS_OUT * 64)                           // out float4 per batch
#define PER_B_IN4    (NV * 64)                                 // x float4 per batch

#define COPY4        (BATCH * PER_B_IN4)                       // 8,294,400 (pure memcpy slots)
#define COPY_BLOCKS  (COPY4 / 1024)                            // 8100 exact (4 slots/thr)
#define GATHER4      (BATCH * NUM_NEW * 64)                    // 24,699,136
#define GATHER_BLOCKS ((GATHER4 + 511) / 512)                  // 2 slots/thr
#define TOPO_BPB     ((NF_BASE + 255) / 256)                   // 251
#define TOPO_BLOCKS  (TOPO_BPB * BATCH)                        // 1004

// Analytic endpoints of the j-th new edge (first-occurrence order).
__device__ __forceinline__ void edge_endpoints(int j, int& p0, int& p1) {
    if (j < B0) {
        int q = j / 3;
        int t = j - q * 3;
        int r = q / 179;
        int cc = q - r * 179;
        int v00 = r * GRID_G + cc;
        if (t == 0)      { p0 = v00;       p1 = v00 + 1;   }      // H(r,cc)
        else if (t == 1) { p0 = v00 + 1;   p1 = v00 + 181; }      // V(r,cc+1)
        else             { p0 = v00;       p1 = v00 + 181; }      // D(r,cc)
    } else {
        int m = j - B0;
        if (m <= 177)      { p0 = m * GRID_G;       p1 = (m + 1) * GRID_G; }     // V(m,0)
        else if (m == 178) { p0 = 179 * GRID_G;     p1 = 179 * GRID_G + 1; }     // H(179,0)
        else if (m == 179) { p0 = 178 * GRID_G;     p1 = 179 * GRID_G;     }     // V(178,0)
        else { int cc = m - 179; p0 = 179 * GRID_G + cc; p1 = p0 + 1; }          // H(179,cc)
    }
}

__device__ __forceinline__ void gather_slot(const float4* __restrict__ x,
                                            float4* __restrict__ out, int s) {
    const int per_b = NUM_NEW * 64;
    int b   = s / per_b;
    int rem = s - b * per_b;
    int j   = rem >> 6;
    int q   = rem & 63;

    int p0, p1;
    edge_endpoints(j, p0, p1);

    const float4* xb = x + (size_t)b * PER_B_IN4;
    float4 a = __ldg(&xb[p0 * 64 + q]);
    float4 c = __ldg(&xb[p1 * 64 + q]);
    float4 r4;
    r4.x = 0.5f * (a.x + c.x);
    r4.y = 0.5f * (a.y + c.y);
    r4.z = 0.5f * (a.z + c.z);
    r4.w = 0.5f * (a.w + c.w);
    __stcs(&out[(size_t)b * PER_B_OUT4 + (NV + j) * 64 + q], r4);
}

__device__ __forceinline__ void topo_face(float* __restrict__ out, int f, int b) {
    int v0, v1, v2, n0, n1, n2;
    if (f < CELLS) {
        int c = f;
        int r = c / 179, cc = c - r * 179;
        int v00 = r * GRID_G + cc;
        v0 = v00; v1 = v00 + 1; v2 = v00 + 181;
        n0 = NV + 3 * c;        // H(r,cc)
        n1 = NV + 3 * c + 1;    // V(r,cc+1)
        n2 = NV + 3 * c + 2;    // D(r,cc)
    } else {
        int c = f - CELLS;
        int r = c / 179, cc = c - r * 179;
        int v00 = r * GRID_G + cc;
        v0 = v00; v1 = v00 + 181; v2 = v00 + 180;
        n0 = NV + 3 * c + 2;    // D(r,cc)
        if (r < 178) n1 = NV + 3 * ((r + 1) * 179 + cc);
        else         n1 = (cc == 0) ? (NV + B0 + 178) : (NV + B0 + 179 + cc);
        if (cc >= 1) n2 = NV + 3 * (r * 179 + cc - 1) + 1;
        else         n2 = (r <= 177) ? (NV + B0 + r) : (NV + B0 + 179);
    }

    float* nf  = out + OUT_FEAT_ELEMS + (size_t)b * NFACES4 * 3;
    float* ne0 = out + OUT_FEAT_ELEMS + OUT_NF_ELEMS + (size_t)b * 2 * NEDGE;
    float* ne1 = ne0 + NEDGE;

    int ta[4] = { v0, n0, n1, n0 };
    int tb[4] = { n0, v1, v2, n1 };
    int tc[4] = { n2, n1, n2, n2 };
    int rows[4] = { f, NF_BASE + f, 2 * NF_BASE + f, 3 * NF_BASE + f };

#pragma unroll
    for (int k = 0; k < 4; k++) {
        int g = rows[k];
        float A = (float)ta[k], Bv = (float)tb[k], Cv = (float)tc[k];
        __stcs(&nf[3 * g],     A);
        __stcs(&nf[3 * g + 1], Bv);
        __stcs(&nf[3 * g + 2], Cv);
        __stcs(&ne0[g],               A);
        __stcs(&ne0[4 * NF_BASE + g], Bv);
        __stcs(&ne0[8 * NF_BASE + g], Cv);
        __stcs(&ne1[g],               Bv);
        __stcs(&ne1[4 * NF_BASE + g], Cv);
        __stcs(&ne1[8 * NF_BASE + g], A);
    }
}

// Three specialized block ranges in one launch:
//   [0, TOPO)               : topology writes (overlap everything)
//   [TOPO, TOPO+COPY)       : pure memcpy of x rows, 4 float4/thread, no branches
//   [TOPO+COPY, ...)        : edge-mean gather, 2 float4 slots/thread
__global__ void __launch_bounds__(256) fused_kernel(const float4* __restrict__ x,
                                                    float* __restrict__ out) {
    unsigned bx = blockIdx.x;
    if (bx < TOPO_BLOCKS) {
        int b = bx / TOPO_BPB;
        int f = (bx - b * TOPO_BPB) * 256 + threadIdx.x;
        if (f < NF_BASE) topo_face(out, f, b);
    } else if (bx < TOPO_BLOCKS + COPY_BLOCKS) {
        // Pure streaming copy. Exact tiling: 1024 slots per block.
        int s0 = (bx - TOPO_BLOCKS) * 1024 + threadIdx.x;
        int b   = s0 / PER_B_IN4;
        int rem = s0 - b * PER_B_IN4;
        // One block never straddles a batch boundary fully unrolled? It can.
        // Handle each slot independently (b recomputed cheaply via carry check).
        float4* out4 = (float4*)out;
        float4 v[4];
        int bi[4], ri[4];
#pragma unroll
        for (int k = 0; k < 4; k++) {
            int rr = rem + k * 256;
            int bb = b + (rr >= PER_B_IN4 ? 1 : 0);
            rr -= (rr >= PER_B_IN4 ? PER_B_IN4 : 0);
            bi[k] = bb; ri[k] = rr;
            v[k] = __ldcg(&x[(size_t)bb * PER_B_IN4 + rr]);
        }
#pragma unroll
        for (int k = 0; k < 4; k++)
            __stcs(&out4[(size_t)bi[k] * PER_B_OUT4 + ri[k]], v[k]);
    } else {
        int s = (bx - TOPO_BLOCKS - COPY_BLOCKS) * 512 + threadIdx.x;
        if (s < GATHER4) gather_slot(x, (float4*)out, s);
        int s2 = s + 256;
        if (s2 < GATHER4) gather_slot(x, (float4*)out, s2);
    }
}

extern "C" void kernel_launch(void* const* d_in, const int* in_sizes, int n_in,
                              void* d_out, int out_size) {
    const float4* x = (const float4*)d_in[0];   // x (4, 32400, 256) f32
    float* out = (float*)d_out;
    fused_kernel<<<TOPO_BLOCKS + COPY_BLOCKS + GATHER_BLOCKS, 256>>>(x, out);
}